// round 11
// baseline (speedup 1.0000x reference)
#include <cuda_runtime.h>
#include <math.h>
#include <stdint.h>

// Problem constants
#define Bn 32
#define Tn 40
#define Pn 12
#define En 2048
#define Hn 1024
#define ADIM 9
#define ACTDIM 8
#define M1 (Bn*Tn*Pn)      // 15360 rows (b,t,p)
#define BTn (Bn*Tn)        // 1280
#define GRUR (Bn*Pn)       // 384 GRU rows

// Scratch (__device__ globals: allocation-free, graph-capturable)
__device__ float g_x  [(size_t)M1 * Hn];            // embed output    (~63 MB)
__device__ float g_gx [(size_t)M1 * 3 * Hn];        // input gates     (~189 MB)
__device__ float g_hid[(size_t)M1 * Hn];            // hiddens         (~63 MB)
__device__ float g_gh [2 * (size_t)GRUR * 3 * Hn];  // split-K partial gh (9.4 MB)

__device__ __forceinline__ float sigmoidf_(float x) {
    return 1.0f / (1.0f + expf(-x));
}

__device__ __forceinline__ uint32_t smem_u32(const void* p) {
    return (uint32_t)__cvta_generic_to_shared(p);
}
__device__ __forceinline__ void cp_async16(uint32_t dst, const void* src) {
    asm volatile("cp.async.cg.shared.global [%0], [%1], 16;\n" :: "r"(dst), "l"(src));
}
__device__ __forceinline__ void cp_commit() {
    asm volatile("cp.async.commit_group;\n" ::: "memory");
}
template<int N> __device__ __forceinline__ void cp_wait() {
    asm volatile("cp.async.wait_group %0;\n" :: "n"(N) : "memory");
}

// ---------------------------------------------------------------------------
// NT GEMM v2: C[M,N] = act(A[M,K] @ B[N,K]^T + bias[N])
// 128x128 tile, K-tile 8, register-staged prefetch + double-buffered smem,
// ONE __syncthreads per K-tile. 256 threads, 8x8 fragments.
// Requires M%128==0, N%128==0, K%8==0.
// ---------------------------------------------------------------------------
template<int ACT>  // 0 = none, 1 = tanh
__global__ __launch_bounds__(256, 2) void gemm_nt(
    const float* __restrict__ A, const float* __restrict__ Bw,
    const float* __restrict__ bias, float* __restrict__ C,
    int M, int N, int K)
{
    __shared__ float As[2][8][132];
    __shared__ float Bs[2][8][132];

    const int tid = threadIdx.x;
    const int m0 = blockIdx.y * 128;
    const int n0 = blockIdx.x * 128;
    const int tx = tid & 15;   // col group
    const int ty = tid >> 4;   // row group

    // Loader mapping: one float4 of A and one of B per thread per K-tile.
    const int lrow = tid >> 1;            // 0..127
    const int lkq  = (tid & 1) * 4;       // 0 or 4
    const float* aptr = A  + (size_t)(m0 + lrow) * K + lkq;
    const float* bptr = Bw + (size_t)(n0 + lrow) * K + lkq;

    float acc[8][8];
    #pragma unroll
    for (int i = 0; i < 8; i++)
        #pragma unroll
        for (int j = 0; j < 8; j++) acc[i][j] = 0.0f;

    const int NT = K >> 3;
    // Prologue: fetch tile 0 into registers
    float4 va = *(const float4*)(aptr);
    float4 vb = *(const float4*)(bptr);

    for (int kt = 0; kt < NT; kt++) {
        const int buf = kt & 1;
        // Stage current tile into smem (transposed, conflict-free)
        As[buf][lkq+0][lrow] = va.x; As[buf][lkq+1][lrow] = va.y;
        As[buf][lkq+2][lrow] = va.z; As[buf][lkq+3][lrow] = va.w;
        Bs[buf][lkq+0][lrow] = vb.x; Bs[buf][lkq+1][lrow] = vb.y;
        Bs[buf][lkq+2][lrow] = vb.z; Bs[buf][lkq+3][lrow] = vb.w;
        __syncthreads();

        // Prefetch next tile into registers (overlaps with compute below)
        if (kt + 1 < NT) {
            int k0 = (kt + 1) * 8;
            va = *(const float4*)(aptr + k0);
            vb = *(const float4*)(bptr + k0);
        }

        #pragma unroll
        for (int kk = 0; kk < 8; kk++) {
            float4 a0 = *(const float4*)&As[buf][kk][ty * 4];
            float4 a1 = *(const float4*)&As[buf][kk][64 + ty * 4];
            float4 b0 = *(const float4*)&Bs[buf][kk][tx * 4];
            float4 b1 = *(const float4*)&Bs[buf][kk][64 + tx * 4];
            float av[8] = {a0.x,a0.y,a0.z,a0.w,a1.x,a1.y,a1.z,a1.w};
            float bv[8] = {b0.x,b0.y,b0.z,b0.w,b1.x,b1.y,b1.z,b1.w};
            #pragma unroll
            for (int i = 0; i < 8; i++)
                #pragma unroll
                for (int j = 0; j < 8; j++)
                    acc[i][j] = fmaf(av[i], bv[j], acc[i][j]);
        }
        // No trailing sync: next iteration writes the OTHER buffer; the
        // per-iteration sync above bounds warp skew to one segment.
    }

    #pragma unroll
    for (int i = 0; i < 8; i++) {
        int row = m0 + ((i < 4) ? (ty * 4 + i) : (64 + ty * 4 + (i - 4)));
        #pragma unroll
        for (int j = 0; j < 8; j++) {
            int col = n0 + ((j < 4) ? (tx * 4 + j) : (64 + tx * 4 + (j - 4)));
            float v = acc[i][j] + bias[col];
            if (ACT) v = tanhf(v);
            C[(size_t)row * N + col] = v;
        }
    }
}

// ---------------------------------------------------------------------------
// GRU step GEMM (split-K): partial gh[ks] = h_{t-1}[rows, kb:kb+512] @ W_hh^T
// Tile: 64 rows x 32 cols x 3 gates, 128 threads, per-thread R=8 x C=2 x 3g.
// Grid: (32, 6, 2) = 384 blocks. __launch_bounds__(128,3) -> 12 warps/SM.
// ---------------------------------------------------------------------------
#define RT 64
#define CT 32
#define KSPL 512
#define KTT 32
#define NSUB (KSPL / KTT)   // 16

__global__ __launch_bounds__(128, 3) void gru_gemm(
    const float* __restrict__ W_hh, int t, float* __restrict__ gh)
{
    __shared__ float Hs[2][RT][36];        // 2 x 9216 B
    __shared__ float Ws[2][3][CT][36];     // 2 x 13824 B

    const int tid  = threadIdx.x;
    const int n0   = blockIdx.x * CT;
    const int m0   = blockIdx.y * RT;
    const int kb   = blockIdx.z * KSPL;
    const int colg = tid & 15;   // cols colg, colg+16
    const int rowg = tid >> 4;   // rows rowg + 8*i

    float acc[3][8][2];
    #pragma unroll
    for (int g = 0; g < 3; g++)
        #pragma unroll
        for (int i = 0; i < 8; i++) { acc[g][i][0] = 0.0f; acc[g][i][1] = 0.0f; }

    // ---- loader setup ----
    const float* hsrc[4]; uint32_t hdst[4];
    {
        const int hlk = (tid & 7) * 4;
        #pragma unroll
        for (int l = 0; l < 4; l++) {
            int row = (tid >> 3) + 16 * l;          // 0..63
            int gi = m0 + row;
            int b = gi / Pn, p = gi % Pn;
            hsrc[l] = g_hid + (size_t)((b * Tn + (t - 1)) * Pn + p) * Hn + kb + hlk;
            hdst[l] = smem_u32(&Hs[0][row][hlk]);
        }
    }
    const float* wsrc[6]; uint32_t wdst[6];
    #pragma unroll
    for (int l = 0; l < 6; l++) {
        int id  = tid + 128 * l;       // 0..767
        int g   = id >> 8;
        int rem = id & 255;
        int col = rem >> 3;            // 0..31
        int lk  = (rem & 7) * 4;
        wsrc[l] = W_hh + (size_t)(g * Hn + n0 + col) * Hn + kb + lk;
        wdst[l] = smem_u32(&Ws[0][g][col][lk]);
    }
    const uint32_t hstr = RT * 36 * 4;         // 9216
    const uint32_t wstr = 3 * CT * 36 * 4;     // 13824

    // Prologue: subtile 0 -> buffer 0
    #pragma unroll
    for (int l = 0; l < 4; l++) cp_async16(hdst[l], hsrc[l]);
    #pragma unroll
    for (int l = 0; l < 6; l++) cp_async16(wdst[l], wsrc[l]);
    cp_commit();

    for (int kt = 0; kt < NSUB; kt++) {
        if (kt + 1 < NSUB) {
            const uint32_t nb = (uint32_t)((kt + 1) & 1);
            const int k0 = (kt + 1) * KTT;
            #pragma unroll
            for (int l = 0; l < 4; l++) cp_async16(hdst[l] + nb * hstr, hsrc[l] + k0);
            #pragma unroll
            for (int l = 0; l < 6; l++) cp_async16(wdst[l] + nb * wstr, wsrc[l] + k0);
            cp_commit();
            cp_wait<1>();
        } else {
            cp_wait<0>();
        }
        __syncthreads();

        const int buf = kt & 1;
        #pragma unroll 4
        for (int kk = 0; kk < KTT; kk += 2) {
            float2 h[8];
            #pragma unroll
            for (int i = 0; i < 8; i++)
                h[i] = *(const float2*)&Hs[buf][rowg + 8 * i][kk];
            #pragma unroll
            for (int g = 0; g < 3; g++) {
                float2 w0 = *(const float2*)&Ws[buf][g][colg][kk];
                float2 w1 = *(const float2*)&Ws[buf][g][colg + 16][kk];
                #pragma unroll
                for (int i = 0; i < 8; i++) {
                    acc[g][i][0] = fmaf(h[i].y, w0.y, fmaf(h[i].x, w0.x, acc[g][i][0]));
                    acc[g][i][1] = fmaf(h[i].y, w1.y, fmaf(h[i].x, w1.x, acc[g][i][1]));
                }
            }
        }
        __syncthreads();
    }

    // Epilogue: write partials
    float* ghp = gh + (size_t)blockIdx.z * GRUR * 3 * Hn;
    #pragma unroll
    for (int g = 0; g < 3; g++)
        #pragma unroll
        for (int i = 0; i < 8; i++) {
            int row = m0 + rowg + 8 * i;
            float* dst = ghp + (size_t)row * (3 * Hn) + g * Hn + n0 + colg;
            dst[0]  = acc[g][i][0];
            dst[16] = acc[g][i][1];
        }
}

// ---------------------------------------------------------------------------
// GRU gate math: combine split-K partials + gx + biases, produce h_t.
// One block per GRU row (384 blocks), 256 threads, float4 per thread.
// ---------------------------------------------------------------------------
__global__ __launch_bounds__(256) void gru_gate(
    const float* __restrict__ gh, const float* __restrict__ b_hh, int t)
{
    const int i = blockIdx.x;            // 0..383
    const int b = i / Pn, p = i % Pn;
    const int c = threadIdx.x * 4;       // 0..1020

    const float* gxr  = g_gx  + (size_t)((b * Tn + t) * Pn + p) * 3 * Hn;
    float*       hout = g_hid + (size_t)((b * Tn + t) * Pn + p) * Hn;

    float4 xr = *(const float4*)(gxr + c);
    float4 xz = *(const float4*)(gxr + Hn + c);
    float4 xn = *(const float4*)(gxr + 2 * Hn + c);

    float4 hr = *(const float4*)(b_hh + c);
    float4 hz = *(const float4*)(b_hh + Hn + c);
    float4 hn = *(const float4*)(b_hh + 2 * Hn + c);
    float4 hp = make_float4(0.f, 0.f, 0.f, 0.f);

    if (t > 0) {
        const float* g0 = gh + (size_t)i * (3 * Hn);
        const float* g1 = g0 + (size_t)GRUR * 3 * Hn;
        float4 a, d;
        a = *(const float4*)(g0 + c);            d = *(const float4*)(g1 + c);
        hr.x += a.x + d.x; hr.y += a.y + d.y; hr.z += a.z + d.z; hr.w += a.w + d.w;
        a = *(const float4*)(g0 + Hn + c);       d = *(const float4*)(g1 + Hn + c);
        hz.x += a.x + d.x; hz.y += a.y + d.y; hz.z += a.z + d.z; hz.w += a.w + d.w;
        a = *(const float4*)(g0 + 2 * Hn + c);   d = *(const float4*)(g1 + 2 * Hn + c);
        hn.x += a.x + d.x; hn.y += a.y + d.y; hn.z += a.z + d.z; hn.w += a.w + d.w;
        hp = *(const float4*)(g_hid + (size_t)((b * Tn + (t - 1)) * Pn + p) * Hn + c);
    }

    float4 o;
    {
        float r = sigmoidf_(xr.x + hr.x), z = sigmoidf_(xz.x + hz.x);
        float nn = tanhf(xn.x + r * hn.x);
        o.x = (1.0f - z) * nn + z * hp.x;
    }
    {
        float r = sigmoidf_(xr.y + hr.y), z = sigmoidf_(xz.y + hz.y);
        float nn = tanhf(xn.y + r * hn.y);
        o.y = (1.0f - z) * nn + z * hp.y;
    }
    {
        float r = sigmoidf_(xr.z + hr.z), z = sigmoidf_(xz.z + hz.z);
        float nn = tanhf(xn.z + r * hn.z);
        o.z = (1.0f - z) * nn + z * hp.z;
    }
    {
        float r = sigmoidf_(xr.w + hr.w), z = sigmoidf_(xz.w + hz.w);
        float nn = tanhf(xn.w + r * hn.w);
        o.w = (1.0f - z) * nn + z * hp.w;
    }
    *(float4*)(hout + c) = o;
}

// ---------------------------------------------------------------------------
// Action head: out[row, a] = hiddens[row,:] . W_act[a,:] + b_act[a]
// ---------------------------------------------------------------------------
__global__ __launch_bounds__(256) void action_head(
    const float* __restrict__ W_act, const float* __restrict__ b_act,
    float* __restrict__ out)
{
    __shared__ float Ws[ADIM][Hn];   // 36 KB
    for (int i = threadIdx.x; i < ADIM * Hn; i += 256)
        Ws[i >> 10][i & (Hn - 1)] = W_act[i];
    __syncthreads();

    int warp = threadIdx.x >> 5, lane = threadIdx.x & 31;
    int row = blockIdx.x * 8 + warp;             // < 15360
    const float* h = g_hid + (size_t)row * Hn;

    float acc[ADIM];
    #pragma unroll
    for (int a = 0; a < ADIM; a++) acc[a] = 0.0f;

    for (int k = lane; k < Hn; k += 32) {
        float v = h[k];
        #pragma unroll
        for (int a = 0; a < ADIM; a++) acc[a] = fmaf(v, Ws[a][k], acc[a]);
    }
    #pragma unroll
    for (int a = 0; a < ADIM; a++)
        #pragma unroll
        for (int off = 16; off; off >>= 1)
            acc[a] += __shfl_down_sync(0xffffffffu, acc[a], off);

    if (lane == 0) {
        #pragma unroll
        for (int a = 0; a < ADIM; a++)
            out[(size_t)row * ADIM + a] = acc[a] + b_act[a];
    }
}

// ---------------------------------------------------------------------------
// Activity head: pooled = max over P of hiddens; out = pooled @ W_activ^T + b
// ---------------------------------------------------------------------------
__global__ __launch_bounds__(256) void activity_head(
    const float* __restrict__ W_activ, const float* __restrict__ b_activ,
    float* __restrict__ out)
{
    __shared__ float Ws[ACTDIM][Hn];  // 32 KB
    for (int i = threadIdx.x; i < ACTDIM * Hn; i += 256)
        Ws[i >> 10][i & (Hn - 1)] = W_activ[i];
    __syncthreads();

    int warp = threadIdx.x >> 5, lane = threadIdx.x & 31;
    int row = blockIdx.x * 8 + warp;               // < 1280 = B*T
    const float* hb = g_hid + (size_t)row * Pn * Hn;

    float acc[ACTDIM];
    #pragma unroll
    for (int a = 0; a < ACTDIM; a++) acc[a] = 0.0f;

    for (int k = lane; k < Hn; k += 32) {
        float m = hb[k];
        #pragma unroll
        for (int p = 1; p < Pn; p++) m = fmaxf(m, hb[(size_t)p * Hn + k]);
        #pragma unroll
        for (int a = 0; a < ACTDIM; a++) acc[a] = fmaf(m, Ws[a][k], acc[a]);
    }
    #pragma unroll
    for (int a = 0; a < ACTDIM; a++)
        #pragma unroll
        for (int off = 16; off; off >>= 1)
            acc[a] += __shfl_down_sync(0xffffffffu, acc[a], off);

    if (lane == 0) {
        #pragma unroll
        for (int a = 0; a < ACTDIM; a++)
            out[(size_t)row * ACTDIM + a] = acc[a] + b_activ[a];
    }
}

// ---------------------------------------------------------------------------
extern "C" void kernel_launch(void* const* d_in, const int* in_sizes, int n_in,
                              void* d_out, int out_size)
{
    const float* feature = (const float*)d_in[0];
    const float* W_embed = (const float*)d_in[1];
    const float* b_embed = (const float*)d_in[2];
    const float* W_ih    = (const float*)d_in[3];
    const float* W_hh    = (const float*)d_in[4];
    const float* b_ih    = (const float*)d_in[5];
    const float* b_hh    = (const float*)d_in[6];
    const float* W_act   = (const float*)d_in[7];
    const float* b_act   = (const float*)d_in[8];
    const float* W_activ = (const float*)d_in[9];
    const float* b_activ = (const float*)d_in[10];
    float* out = (float*)d_out;

    float *x_ptr, *gx_ptr, *gh_ptr;
    cudaGetSymbolAddress((void**)&x_ptr,  g_x);
    cudaGetSymbolAddress((void**)&gx_ptr, g_gx);
    cudaGetSymbolAddress((void**)&gh_ptr, g_gh);

    // 1) x = tanh(feature @ W_embed^T + b_embed)   [15360 x 1024]
    gemm_nt<1><<<dim3(Hn / 128, M1 / 128), 256>>>(
        feature, W_embed, b_embed, x_ptr, M1, Hn, En);

    // 2) gx = x @ W_ih^T + b_ih                     [15360 x 3072]
    gemm_nt<0><<<dim3(3 * Hn / 128, M1 / 128), 256>>>(
        x_ptr, W_ih, b_ih, gx_ptr, M1, 3 * Hn, Hn);

    // 3) GRU scan: split-K GEMM + gate kernel per timestep
    gru_gate<<<GRUR, 256>>>(gh_ptr, b_hh, 0);   // t=0: h = f(gx, b_hh) only
    for (int t = 1; t < Tn; t++) {
        gru_gemm<<<dim3(Hn / CT, GRUR / RT, 2), 128>>>(W_hh, t, gh_ptr);
        gru_gate<<<GRUR, 256>>>(gh_ptr, b_hh, t);
    }

    // 4) Heads (outputs concatenated: action [15360x9] then activity [1280x8])
    action_head<<<M1 / 8, 256>>>(W_act, b_act, out);
    activity_head<<<BTn / 8, 256>>>(W_activ, b_activ, out + (size_t)M1 * ADIM);
}

// round 16
// speedup vs baseline: 1.1041x; 1.1041x over previous
#include <cuda_runtime.h>
#include <math.h>
#include <stdint.h>

// Problem constants
#define Bn 32
#define Tn 40
#define Pn 12
#define En 2048
#define Hn 1024
#define ADIM 9
#define ACTDIM 8
#define M1 (Bn*Tn*Pn)      // 15360 rows (b,t,p)
#define BTn (Bn*Tn)        // 1280
#define GRUR (Bn*Pn)       // 384 GRU rows

// Scratch (__device__ globals: allocation-free, graph-capturable)
__device__ float g_x  [(size_t)M1 * Hn];            // embed output    (~63 MB)
__device__ float g_gx [(size_t)M1 * 3 * Hn];        // input gates     (~189 MB)
__device__ float g_hid[(size_t)M1 * Hn];            // hiddens         (~63 MB)
__device__ float g_gh [2 * (size_t)GRUR * 3 * Hn];  // split-K partial gh

__device__ __forceinline__ float sigmoidf_(float x) {
    return 1.0f / (1.0f + expf(-x));
}
__device__ __forceinline__ uint32_t smem_u32(const void* p) {
    return (uint32_t)__cvta_generic_to_shared(p);
}
__device__ __forceinline__ void cp_async16(uint32_t dst, const void* src) {
    asm volatile("cp.async.cg.shared.global [%0], [%1], 16;\n" :: "r"(dst), "l"(src));
}
__device__ __forceinline__ void cp_commit() {
    asm volatile("cp.async.commit_group;\n" ::: "memory");
}
template<int N> __device__ __forceinline__ void cp_wait() {
    asm volatile("cp.async.wait_group %0;\n" :: "n"(N) : "memory");
}

// ---------------------------------------------------------------------------
// NT GEMM (R3/R5 proven): C[M,N] = act(A[M,K] @ B[N,K]^T + bias[N])
// Tiles: 128x128x16, 256 threads, 8x8 per-thread fragments.
// ---------------------------------------------------------------------------
template<int ACT>  // 0 = none, 1 = tanh
__global__ __launch_bounds__(256) void gemm_nt(
    const float* __restrict__ A, const float* __restrict__ Bw,
    const float* __restrict__ bias, float* __restrict__ C,
    int M, int N, int K)
{
    __shared__ float As[16][132];
    __shared__ float Bs[16][132];

    const int tid = threadIdx.x;
    const int m0 = blockIdx.y * 128;
    const int n0 = blockIdx.x * 128;
    const int tx = tid & 15;   // col group
    const int ty = tid >> 4;   // row group

    float acc[8][8];
    #pragma unroll
    for (int i = 0; i < 8; i++)
        #pragma unroll
        for (int j = 0; j < 8; j++) acc[i][j] = 0.0f;

    for (int k0 = 0; k0 < K; k0 += 16) {
        #pragma unroll
        for (int l = 0; l < 2; l++) {
            int lin = tid + l * 256;          // 0..511
            int row = lin >> 2;               // 0..127
            int kq  = (lin & 3) * 4;          // 0,4,8,12
            float4 va = *(const float4*)(A  + (size_t)(m0 + row) * K + k0 + kq);
            As[kq+0][row] = va.x; As[kq+1][row] = va.y;
            As[kq+2][row] = va.z; As[kq+3][row] = va.w;
            float4 vb = *(const float4*)(Bw + (size_t)(n0 + row) * K + k0 + kq);
            Bs[kq+0][row] = vb.x; Bs[kq+1][row] = vb.y;
            Bs[kq+2][row] = vb.z; Bs[kq+3][row] = vb.w;
        }
        __syncthreads();

        #pragma unroll
        for (int kk = 0; kk < 16; kk++) {
            float4 a0 = *(const float4*)&As[kk][ty * 4];
            float4 a1 = *(const float4*)&As[kk][64 + ty * 4];
            float4 b0 = *(const float4*)&Bs[kk][tx * 4];
            float4 b1 = *(const float4*)&Bs[kk][64 + tx * 4];
            float av[8] = {a0.x,a0.y,a0.z,a0.w,a1.x,a1.y,a1.z,a1.w};
            float bv[8] = {b0.x,b0.y,b0.z,b0.w,b1.x,b1.y,b1.z,b1.w};
            #pragma unroll
            for (int i = 0; i < 8; i++)
                #pragma unroll
                for (int j = 0; j < 8; j++)
                    acc[i][j] = fmaf(av[i], bv[j], acc[i][j]);
        }
        __syncthreads();
    }

    #pragma unroll
    for (int i = 0; i < 8; i++) {
        int row = m0 + ((i < 4) ? (ty * 4 + i) : (64 + ty * 4 + (i - 4)));
        #pragma unroll
        for (int j = 0; j < 8; j++) {
            int col = n0 + ((j < 4) ? (tx * 4 + j) : (64 + tx * 4 + (j - 4)));
            float v = acc[i][j] + bias[col];
            if (ACT) v = tanhf(v);
            C[(size_t)row * N + col] = v;
        }
    }
}

// ---------------------------------------------------------------------------
// GRU step GEMM (split-K) — proven R5 config (64.7us measured).
// Tile 64x32x3gates, 128 threads, grid (32, 6, 2).
// ---------------------------------------------------------------------------
#define RT 64
#define CT 32
#define KSPL 512
#define KTT 32
#define NSUB (KSPL / KTT)   // 16

__global__ __launch_bounds__(128) void gru_gemm(
    const float* __restrict__ W_hh, int t, float* __restrict__ gh)
{
    __shared__ float Hs[2][RT][36];        // 2 x 9216 B
    __shared__ float Ws[2][3][CT][36];     // 2 x 13824 B

    const int tid  = threadIdx.x;
    const int n0   = blockIdx.x * CT;
    const int m0   = blockIdx.y * RT;
    const int kb   = blockIdx.z * KSPL;
    const int colg = tid & 15;
    const int rowg = tid >> 4;

    float acc[3][8][2];
    #pragma unroll
    for (int g = 0; g < 3; g++)
        #pragma unroll
        for (int i = 0; i < 8; i++) { acc[g][i][0] = 0.0f; acc[g][i][1] = 0.0f; }

    const float* hsrc[4]; uint32_t hdst[4];
    {
        const int hlk = (tid & 7) * 4;
        #pragma unroll
        for (int l = 0; l < 4; l++) {
            int row = (tid >> 3) + 16 * l;
            int gi = m0 + row;
            int b = gi / Pn, p = gi % Pn;
            hsrc[l] = g_hid + (size_t)((b * Tn + (t - 1)) * Pn + p) * Hn + kb + hlk;
            hdst[l] = smem_u32(&Hs[0][row][hlk]);
        }
    }
    const float* wsrc[6]; uint32_t wdst[6];
    #pragma unroll
    for (int l = 0; l < 6; l++) {
        int id  = tid + 128 * l;
        int g   = id >> 8;
        int rem = id & 255;
        int col = rem >> 3;
        int lk  = (rem & 7) * 4;
        wsrc[l] = W_hh + (size_t)(g * Hn + n0 + col) * Hn + kb + lk;
        wdst[l] = smem_u32(&Ws[0][g][col][lk]);
    }
    const uint32_t hstr = RT * 36 * 4;
    const uint32_t wstr = 3 * CT * 36 * 4;

    #pragma unroll
    for (int l = 0; l < 4; l++) cp_async16(hdst[l], hsrc[l]);
    #pragma unroll
    for (int l = 0; l < 6; l++) cp_async16(wdst[l], wsrc[l]);
    cp_commit();

    for (int kt = 0; kt < NSUB; kt++) {
        if (kt + 1 < NSUB) {
            const uint32_t nb = (uint32_t)((kt + 1) & 1);
            const int k0 = (kt + 1) * KTT;
            #pragma unroll
            for (int l = 0; l < 4; l++) cp_async16(hdst[l] + nb * hstr, hsrc[l] + k0);
            #pragma unroll
            for (int l = 0; l < 6; l++) cp_async16(wdst[l] + nb * wstr, wsrc[l] + k0);
            cp_commit();
            cp_wait<1>();
        } else {
            cp_wait<0>();
        }
        __syncthreads();

        const int buf = kt & 1;
        #pragma unroll 4
        for (int kk = 0; kk < KTT; kk += 2) {
            float2 h[8];
            #pragma unroll
            for (int i = 0; i < 8; i++)
                h[i] = *(const float2*)&Hs[buf][rowg + 8 * i][kk];
            #pragma unroll
            for (int g = 0; g < 3; g++) {
                float2 w0 = *(const float2*)&Ws[buf][g][colg][kk];
                float2 w1 = *(const float2*)&Ws[buf][g][colg + 16][kk];
                #pragma unroll
                for (int i = 0; i < 8; i++) {
                    acc[g][i][0] = fmaf(h[i].y, w0.y, fmaf(h[i].x, w0.x, acc[g][i][0]));
                    acc[g][i][1] = fmaf(h[i].y, w1.y, fmaf(h[i].x, w1.x, acc[g][i][1]));
                }
            }
        }
        __syncthreads();
    }

    float* ghp = gh + (size_t)blockIdx.z * GRUR * 3 * Hn;
    #pragma unroll
    for (int g = 0; g < 3; g++)
        #pragma unroll
        for (int i = 0; i < 8; i++) {
            int row = m0 + rowg + 8 * i;
            float* dst = ghp + (size_t)row * (3 * Hn) + g * Hn + n0 + colg;
            dst[0]  = acc[g][i][0];
            dst[16] = acc[g][i][1];
        }
}

// ---------------------------------------------------------------------------
// GRU gate math: combine split-K partials + gx + biases, produce h_t.
// ---------------------------------------------------------------------------
__global__ __launch_bounds__(256) void gru_gate(
    const float* __restrict__ gh, const float* __restrict__ b_hh, int t)
{
    const int i = blockIdx.x;
    const int b = i / Pn, p = i % Pn;
    const int c = threadIdx.x * 4;

    const float* gxr  = g_gx  + (size_t)((b * Tn + t) * Pn + p) * 3 * Hn;
    float*       hout = g_hid + (size_t)((b * Tn + t) * Pn + p) * Hn;

    float4 xr = *(const float4*)(gxr + c);
    float4 xz = *(const float4*)(gxr + Hn + c);
    float4 xn = *(const float4*)(gxr + 2 * Hn + c);

    float4 hr = *(const float4*)(b_hh + c);
    float4 hz = *(const float4*)(b_hh + Hn + c);
    float4 hn = *(const float4*)(b_hh + 2 * Hn + c);
    float4 hp = make_float4(0.f, 0.f, 0.f, 0.f);

    if (t > 0) {
        const float* g0 = gh + (size_t)i * (3 * Hn);
        const float* g1 = g0 + (size_t)GRUR * 3 * Hn;
        float4 a, d;
        a = *(const float4*)(g0 + c);            d = *(const float4*)(g1 + c);
        hr.x += a.x + d.x; hr.y += a.y + d.y; hr.z += a.z + d.z; hr.w += a.w + d.w;
        a = *(const float4*)(g0 + Hn + c);       d = *(const float4*)(g1 + Hn + c);
        hz.x += a.x + d.x; hz.y += a.y + d.y; hz.z += a.z + d.z; hz.w += a.w + d.w;
        a = *(const float4*)(g0 + 2 * Hn + c);   d = *(const float4*)(g1 + 2 * Hn + c);
        hn.x += a.x + d.x; hn.y += a.y + d.y; hn.z += a.z + d.z; hn.w += a.w + d.w;
        hp = *(const float4*)(g_hid + (size_t)((b * Tn + (t - 1)) * Pn + p) * Hn + c);
    }

    float4 o;
    {
        float r = sigmoidf_(xr.x + hr.x), z = sigmoidf_(xz.x + hz.x);
        float nn = tanhf(xn.x + r * hn.x);
        o.x = (1.0f - z) * nn + z * hp.x;
    }
    {
        float r = sigmoidf_(xr.y + hr.y), z = sigmoidf_(xz.y + hz.y);
        float nn = tanhf(xn.y + r * hn.y);
        o.y = (1.0f - z) * nn + z * hp.y;
    }
    {
        float r = sigmoidf_(xr.z + hr.z), z = sigmoidf_(xz.z + hz.z);
        float nn = tanhf(xn.z + r * hn.z);
        o.z = (1.0f - z) * nn + z * hp.z;
    }
    {
        float r = sigmoidf_(xr.w + hr.w), z = sigmoidf_(xz.w + hz.w);
        float nn = tanhf(xn.w + r * hn.w);
        o.w = (1.0f - z) * nn + z * hp.w;
    }
    *(float4*)(hout + c) = o;
}

// ---------------------------------------------------------------------------
// Action head
// ---------------------------------------------------------------------------
__global__ __launch_bounds__(256) void action_head(
    const float* __restrict__ W_act, const float* __restrict__ b_act,
    float* __restrict__ out)
{
    __shared__ float Ws[ADIM][Hn];
    for (int i = threadIdx.x; i < ADIM * Hn; i += 256)
        Ws[i >> 10][i & (Hn - 1)] = W_act[i];
    __syncthreads();

    int warp = threadIdx.x >> 5, lane = threadIdx.x & 31;
    int row = blockIdx.x * 8 + warp;
    const float* h = g_hid + (size_t)row * Hn;

    float acc[ADIM];
    #pragma unroll
    for (int a = 0; a < ADIM; a++) acc[a] = 0.0f;

    for (int k = lane; k < Hn; k += 32) {
        float v = h[k];
        #pragma unroll
        for (int a = 0; a < ADIM; a++) acc[a] = fmaf(v, Ws[a][k], acc[a]);
    }
    #pragma unroll
    for (int a = 0; a < ADIM; a++)
        #pragma unroll
        for (int off = 16; off; off >>= 1)
            acc[a] += __shfl_down_sync(0xffffffffu, acc[a], off);

    if (lane == 0) {
        #pragma unroll
        for (int a = 0; a < ADIM; a++)
            out[(size_t)row * ADIM + a] = acc[a] + b_act[a];
    }
}

// ---------------------------------------------------------------------------
// Activity head
// ---------------------------------------------------------------------------
__global__ __launch_bounds__(256) void activity_head(
    const float* __restrict__ W_activ, const float* __restrict__ b_activ,
    float* __restrict__ out)
{
    __shared__ float Ws[ACTDIM][Hn];
    for (int i = threadIdx.x; i < ACTDIM * Hn; i += 256)
        Ws[i >> 10][i & (Hn - 1)] = W_activ[i];
    __syncthreads();

    int warp = threadIdx.x >> 5, lane = threadIdx.x & 31;
    int row = blockIdx.x * 8 + warp;
    const float* hb = g_hid + (size_t)row * Pn * Hn;

    float acc[ACTDIM];
    #pragma unroll
    for (int a = 0; a < ACTDIM; a++) acc[a] = 0.0f;

    for (int k = lane; k < Hn; k += 32) {
        float m = hb[k];
        #pragma unroll
        for (int p = 1; p < Pn; p++) m = fmaxf(m, hb[(size_t)p * Hn + k]);
        #pragma unroll
        for (int a = 0; a < ACTDIM; a++) acc[a] = fmaf(m, Ws[a][k], acc[a]);
    }
    #pragma unroll
    for (int a = 0; a < ACTDIM; a++)
        #pragma unroll
        for (int off = 16; off; off >>= 1)
            acc[a] += __shfl_down_sync(0xffffffffu, acc[a], off);

    if (lane == 0) {
        #pragma unroll
        for (int a = 0; a < ACTDIM; a++)
            out[(size_t)row * ACTDIM + a] = acc[a] + b_activ[a];
    }
}

// ---------------------------------------------------------------------------
extern "C" void kernel_launch(void* const* d_in, const int* in_sizes, int n_in,
                              void* d_out, int out_size)
{
    const float* feature = (const float*)d_in[0];
    const float* W_embed = (const float*)d_in[1];
    const float* b_embed = (const float*)d_in[2];
    const float* W_ih    = (const float*)d_in[3];
    const float* W_hh    = (const float*)d_in[4];
    const float* b_ih    = (const float*)d_in[5];
    const float* b_hh    = (const float*)d_in[6];
    const float* W_act   = (const float*)d_in[7];
    const float* b_act   = (const float*)d_in[8];
    const float* W_activ = (const float*)d_in[9];
    const float* b_activ = (const float*)d_in[10];
    float* out = (float*)d_out;

    float *x_ptr, *gx_ptr, *gh_ptr;
    cudaGetSymbolAddress((void**)&x_ptr,  g_x);
    cudaGetSymbolAddress((void**)&gx_ptr, g_gx);
    cudaGetSymbolAddress((void**)&gh_ptr, g_gh);

    // 1) x = tanh(feature @ W_embed^T + b_embed)   [15360 x 1024]
    gemm_nt<1><<<dim3(Hn / 128, M1 / 128), 256>>>(
        feature, W_embed, b_embed, x_ptr, M1, Hn, En);

    // 2) gx = x @ W_ih^T + b_ih                     [15360 x 3072]
    gemm_nt<0><<<dim3(3 * Hn / 128, M1 / 128), 256>>>(
        x_ptr, W_ih, b_ih, gx_ptr, M1, 3 * Hn, Hn);

    // 3) GRU scan: split-K GEMM + gate kernel per timestep
    gru_gate<<<GRUR, 256>>>(gh_ptr, b_hh, 0);
    for (int t = 1; t < Tn; t++) {
        gru_gemm<<<dim3(Hn / CT, GRUR / RT, 2), 128>>>(W_hh, t, gh_ptr);
        gru_gate<<<GRUR, 256>>>(gh_ptr, b_hh, t);
    }

    // 4) Heads
    action_head<<<M1 / 8, 256>>>(W_act, b_act, out);
    activity_head<<<BTn / 8, 256>>>(W_activ, b_activ, out + (size_t)M1 * ADIM);
}